// round 1
// baseline (speedup 1.0000x reference)
#include <cuda_runtime.h>
#include <math.h>

// Problem shapes (fixed by the dataset)
#define NB 4
#define NT 1024
#define ND 512
#define NH 8
#define NDH 64
#define NR 2047          // 2*T - 1
#define NM 4096          // B*T

// ---------------- device scratch (no allocations allowed) ----------------
__device__ float gQ[NM * ND];
__device__ float gK[NM * ND];
__device__ float gV[NM * ND];
__device__ float gPE[NR * ND];
__device__ float gE[NR * ND];
__device__ float gS[33554432];      // B*H*T*T = 4*8*1024*1024
__device__ float gO[NM * ND];
__device__ float gUK[NB * NH * NT]; // u_bias . K  per (b,h,t)
__device__ float gVE[NH * NR];      // v_bias . E  per (h,r)

// ---------------- relative sinusoidal positional encoding ----------------
// pe_slice[r, 2m]   = sin(p * inv_freq[m]),  p = 1023 - r
// pe_slice[r, 2m+1] = cos(p * inv_freq[m])
__global__ void pe_kernel() {
    int idx = blockIdx.x * 256 + threadIdx.x;
    if (idx >= NR * 256) return;
    int r = idx >> 8;
    int m = idx & 255;
    double inv = exp(-((double)(2 * m) / 512.0) * log(10000.0));
    double ang = (double)(1023 - r) * inv;
    gPE[r * ND + 2 * m]     = (float)sin(ang);
    gPE[r * ND + 2 * m + 1] = (float)cos(ang);
}

// ---------------- C[M,512] = A[M,512] @ W[512,512]^T + bias --------------
// 64x64 tile, BK=16, 256 threads, 4x4 register blocking.
__global__ void sgemm_nt512(const float* __restrict__ A, const float* __restrict__ W,
                            const float* __restrict__ bias, float* __restrict__ C, int M) {
    __shared__ float As[16][68];
    __shared__ float Bs[16][68];
    int tid = threadIdx.x;
    int bm = blockIdx.y * 64, bn = blockIdx.x * 64;
    int tr = (tid >> 4) << 2, tc = (tid & 15) << 2;
    float acc[4][4] = {};
    for (int k0 = 0; k0 < 512; k0 += 16) {
        #pragma unroll
        for (int i = 0; i < 4; i++) {
            int lin = tid + i * 256;
            int m = lin >> 4, kk = lin & 15;
            As[kk][m] = (bm + m < M) ? A[(size_t)(bm + m) * 512 + k0 + kk] : 0.f;
            Bs[kk][m] = W[(size_t)(bn + m) * 512 + k0 + kk];
        }
        __syncthreads();
        #pragma unroll
        for (int kk = 0; kk < 16; kk++) {
            float4 a = *(const float4*)&As[kk][tr];
            float4 w = *(const float4*)&Bs[kk][tc];
            float av[4] = {a.x, a.y, a.z, a.w};
            float wv[4] = {w.x, w.y, w.z, w.w};
            #pragma unroll
            for (int i = 0; i < 4; i++)
                #pragma unroll
                for (int j = 0; j < 4; j++)
                    acc[i][j] += av[i] * wv[j];
        }
        __syncthreads();
    }
    #pragma unroll
    for (int i = 0; i < 4; i++) {
        int row = bm + tr + i;
        if (row < M)
            #pragma unroll
            for (int j = 0; j < 4; j++)
                C[(size_t)row * 512 + bn + tc + j] = acc[i][j] + bias[bn + tc + j];
    }
}

// ---------------- gUK[b,h,t] = sum_d u[h*64+d] * K[b,t,h*64+d] -----------
__global__ void uk_kernel(const float* __restrict__ u) {
    int gid = blockIdx.x * 256 + threadIdx.x;
    int w = gid >> 5, lane = gid & 31;
    if (w >= NB * NH * NT) return;
    int t = w & (NT - 1);
    int bh = w >> 10;
    int h = bh & 7, b = bh >> 3;
    const float* kp = gK + (size_t)(b * NT + t) * ND + h * NDH;
    const float* up = u + h * NDH;
    float s = kp[lane] * up[lane] + kp[lane + 32] * up[lane + 32];
    #pragma unroll
    for (int o = 16; o; o >>= 1) s += __shfl_down_sync(0xffffffffu, s, o);
    if (lane == 0) gUK[bh * NT + t] = s;
}

// ---------------- gVE[h,r] = sum_d v[h*64+d] * E[r,h*64+d] ---------------
__global__ void ve_kernel(const float* __restrict__ v) {
    int gid = blockIdx.x * 256 + threadIdx.x;
    int w = gid >> 5, lane = gid & 31;
    if (w >= NH * NR) return;
    int h = w / NR;
    int r = w - h * NR;
    const float* ep = gE + (size_t)r * ND + h * NDH;
    const float* vp = v + h * NDH;
    float s = ep[lane] * vp[lane] + ep[lane + 32] * vp[lane + 32];
    #pragma unroll
    for (int o = 16; o; o >>= 1) s += __shfl_down_sync(0xffffffffu, s, o);
    if (lane == 0) gVE[h * NR + r] = s;
}

// ---------------- scores: S[b,h,q,k] = (Q.K + Q.E_r + u.K + v.E_r)/8 -----
// Per 64x64 tile: GEMM1 = Q.K^T, then skewed GEMM over a 127-row E band
// (G[q,c] = Q[q].E[rbase+c]) in two 64-col chunks, then diagonal gather
// S_E[q,k] = G[q, k - q + 63].  Dynamic smem: Qs + KEs (reused) + Gs.
__global__ void scores_kernel() {
    extern __shared__ float sm[];
    float* Qs  = sm;                 // [64 d][68]  (d-major, pad 68)
    float* KEs = sm + 64 * 68;       // [64 d][68]  K tile then E chunks
    float* Gs  = sm + 2 * 64 * 68;   // [64 q][132]
    int tid = threadIdx.x;
    int bh = blockIdx.z, h = bh & 7, b = bh >> 3;
    int q0 = blockIdx.y * 64, k0 = blockIdx.x * 64;
    int tr = (tid >> 4) << 2, tc = (tid & 15) << 2;

    #pragma unroll
    for (int i = 0; i < 16; i++) {
        int lin = tid + i * 256;
        int row = lin >> 6, d = lin & 63;
        Qs[d * 68 + row]  = gQ[(size_t)(b * NT + q0 + row) * ND + h * NDH + d];
        KEs[d * 68 + row] = gK[(size_t)(b * NT + k0 + row) * ND + h * NDH + d];
    }
    __syncthreads();

    float acc[4][4] = {};
    #pragma unroll 16
    for (int d = 0; d < 64; d++) {
        float4 a = *(const float4*)&Qs[d * 68 + tr];
        float4 k4 = *(const float4*)&KEs[d * 68 + tc];
        float av[4] = {a.x, a.y, a.z, a.w};
        float kv[4] = {k4.x, k4.y, k4.z, k4.w};
        #pragma unroll
        for (int i = 0; i < 4; i++)
            #pragma unroll
            for (int j = 0; j < 4; j++)
                acc[i][j] += av[i] * kv[j];
    }

    int rbase = 960 + k0 - q0;   // = (T-1) + k0 - q0 - 63, always >= 0
    for (int chunk = 0; chunk < 2; chunk++) {
        __syncthreads();   // protect KEs against in-flight reads
        #pragma unroll
        for (int i = 0; i < 16; i++) {
            int lin = tid + i * 256;
            int c = lin >> 6, d = lin & 63;
            int r = rbase + chunk * 64 + c;
            KEs[d * 68 + c] = (r < NR) ? gE[(size_t)r * ND + h * NDH + d] : 0.f;
        }
        __syncthreads();
        float e[4][4] = {};
        #pragma unroll 16
        for (int d = 0; d < 64; d++) {
            float4 a = *(const float4*)&Qs[d * 68 + tr];
            float4 e4 = *(const float4*)&KEs[d * 68 + tc];
            float av[4] = {a.x, a.y, a.z, a.w};
            float ev[4] = {e4.x, e4.y, e4.z, e4.w};
            #pragma unroll
            for (int i = 0; i < 4; i++)
                #pragma unroll
                for (int j = 0; j < 4; j++)
                    e[i][j] += av[i] * ev[j];
        }
        #pragma unroll
        for (int i = 0; i < 4; i++)
            #pragma unroll
            for (int j = 0; j < 4; j++)
                Gs[(tr + i) * 132 + chunk * 64 + tc + j] = e[i][j];
    }
    __syncthreads();

    #pragma unroll
    for (int i = 0; i < 4; i++) {
        int q = tr + i;
        #pragma unroll
        for (int j = 0; j < 4; j++) {
            int k = tc + j;
            int c = k + 63 - q;                  // r = rbase + c = 1023 + kg - qg
            float s = acc[i][j] + Gs[q * 132 + c]
                    + gUK[bh * NT + k0 + k] + gVE[h * NR + rbase + c];
            gS[(size_t)(bh * NT + q0 + q) * NT + k0 + k] = s * 0.125f;
        }
    }
}

// ---------------- row softmax over 1024 columns --------------------------
__global__ void softmax_kernel() {
    int row = blockIdx.x;
    float* p = gS + (size_t)row * NT;
    int tid = threadIdx.x;
    float4 v = *(float4*)(p + tid * 4);
    __shared__ float red[256];
    float m = fmaxf(fmaxf(v.x, v.y), fmaxf(v.z, v.w));
    red[tid] = m; __syncthreads();
    for (int s = 128; s; s >>= 1) {
        if (tid < s) red[tid] = fmaxf(red[tid], red[tid + s]);
        __syncthreads();
    }
    m = red[0]; __syncthreads();
    v.x = expf(v.x - m); v.y = expf(v.y - m);
    v.z = expf(v.z - m); v.w = expf(v.w - m);
    float sum = v.x + v.y + v.z + v.w;
    red[tid] = sum; __syncthreads();
    for (int s = 128; s; s >>= 1) {
        if (tid < s) red[tid] += red[tid + s];
        __syncthreads();
    }
    float inv = 1.f / red[0];
    v.x *= inv; v.y *= inv; v.z *= inv; v.w *= inv;
    *(float4*)(p + tid * 4) = v;
}

// ---------------- O[b,h,q,:] = P[b,h,q,:] @ V[b,h,:,:] -------------------
__global__ void pv_kernel() {
    __shared__ float Ps[16][68];
    __shared__ float Vs[16][68];
    int bh = blockIdx.y, b = bh >> 3, h = bh & 7;
    int q0 = blockIdx.x * 64;
    int tid = threadIdx.x;
    int tr = (tid >> 4) << 2, tc = (tid & 15) << 2;
    const float* S = gS + (size_t)(bh * NT + q0) * NT;
    float acc[4][4] = {};
    for (int kk0 = 0; kk0 < NT; kk0 += 16) {
        #pragma unroll
        for (int i = 0; i < 4; i++) {
            int lin = tid + i * 256;
            int q = lin >> 4, kk = lin & 15;
            Ps[kk][q] = S[(size_t)q * NT + kk0 + kk];
        }
        #pragma unroll
        for (int i = 0; i < 4; i++) {
            int lin = tid + i * 256;
            int kk = lin >> 6, d = lin & 63;
            Vs[kk][d] = gV[(size_t)(b * NT + kk0 + kk) * ND + h * NDH + d];
        }
        __syncthreads();
        #pragma unroll
        for (int kk = 0; kk < 16; kk++) {
            float4 a = *(const float4*)&Ps[kk][tr];
            float4 vv = *(const float4*)&Vs[kk][tc];
            float av[4] = {a.x, a.y, a.z, a.w};
            float bv[4] = {vv.x, vv.y, vv.z, vv.w};
            #pragma unroll
            for (int i = 0; i < 4; i++)
                #pragma unroll
                for (int j = 0; j < 4; j++)
                    acc[i][j] += av[i] * bv[j];
        }
        __syncthreads();
    }
    #pragma unroll
    for (int i = 0; i < 4; i++)
        #pragma unroll
        for (int j = 0; j < 4; j++)
            gO[(size_t)(b * NT + q0 + tr + i) * ND + h * NDH + tc + j] = acc[i][j];
}

// -------------------------------------------------------------------------
extern "C" void kernel_launch(void* const* d_in, const int* in_sizes, int n_in,
                              void* d_out, int out_size) {
    const float* query = (const float*)d_in[0];
    const float* key_  = (const float*)d_in[1];
    const float* value = (const float*)d_in[2];
    const float* Wq = (const float*)d_in[3];
    const float* bq = (const float*)d_in[4];
    const float* Wk = (const float*)d_in[5];
    const float* bk = (const float*)d_in[6];
    const float* Wv = (const float*)d_in[7];
    const float* bv = (const float*)d_in[8];
    const float* Wp = (const float*)d_in[9];
    const float* bp = (const float*)d_in[10];
    const float* Wo = (const float*)d_in[11];
    const float* bo = (const float*)d_in[12];
    const float* ub = (const float*)d_in[13];
    const float* vb = (const float*)d_in[14];
    float* out = (float*)d_out;

    float *pQ, *pK, *pV, *pPE, *pE, *pO;
    cudaGetSymbolAddress((void**)&pQ, gQ);
    cudaGetSymbolAddress((void**)&pK, gK);
    cudaGetSymbolAddress((void**)&pV, gV);
    cudaGetSymbolAddress((void**)&pPE, gPE);
    cudaGetSymbolAddress((void**)&pE, gE);
    cudaGetSymbolAddress((void**)&pO, gO);

    const int SCORES_SMEM = (2 * 64 * 68 + 64 * 132) * 4;  // 68608 bytes
    cudaFuncSetAttribute(scores_kernel, cudaFuncAttributeMaxDynamicSharedMemorySize, SCORES_SMEM);

    pe_kernel<<<NR, 256>>>();
    sgemm_nt512<<<dim3(8, 64), 256>>>(query, Wq, bq, pQ, NM);
    sgemm_nt512<<<dim3(8, 64), 256>>>(key_,  Wk, bk, pK, NM);
    sgemm_nt512<<<dim3(8, 64), 256>>>(value, Wv, bv, pV, NM);
    sgemm_nt512<<<dim3(8, 32), 256>>>(pPE,   Wp, bp, pE, NR);
    uk_kernel<<<(NB * NH * NT * 32) / 256, 256>>>(ub);
    ve_kernel<<<(NH * NR * 32 + 255) / 256, 256>>>(vb);
    scores_kernel<<<dim3(16, 16, 32), 256, SCORES_SMEM>>>();
    softmax_kernel<<<NB * NH * NT, 256>>>();
    pv_kernel<<<dim3(16, 32), 256>>>();
    sgemm_nt512<<<dim3(8, 64), 256>>>(pO, Wo, bo, out, NM);
}

// round 3
// speedup vs baseline: 1.4409x; 1.4409x over previous
#include <cuda_runtime.h>
#include <math.h>

// Problem shapes (fixed by the dataset)
#define NB 4
#define NT 1024
#define ND 512
#define NH 8
#define NDH 64
#define NR 2047          // 2*T - 1
#define NM 4096          // B*T

#define PADK 36          // pad for [row][k=32] tiles
#define PADD 68          // pad for [row][d=64] tiles

// ---------------- device scratch (no allocations allowed) ----------------
__device__ float gQ[NM * ND];
__device__ float gK[NM * ND];
__device__ float gV[NM * ND];
__device__ float gPE[NR * ND];
__device__ float gE[NR * ND];
__device__ float gS[33554432];      // B*H*T*T
__device__ float gO[NM * ND];
__device__ float gUK[NB * NH * NT];
__device__ float gVE[NH * NR];

// ---------------- tf32 helpers ----------------
__device__ __forceinline__ unsigned f2tf(float f) {
    unsigned r; asm("cvt.rna.tf32.f32 %0,%1;" : "=r"(r) : "f"(f)); return r;
}
__device__ __forceinline__ void cvt_pair(float f, unsigned& hi, unsigned& lo) {
    hi = f2tf(f);
    lo = f2tf(f - __uint_as_float(hi));
}
__device__ __forceinline__ void mma8(float (&c)[4], unsigned a0, unsigned a1,
                                     unsigned a2, unsigned a3, unsigned b0, unsigned b1) {
    asm volatile(
        "mma.sync.aligned.m16n8k8.row.col.f32.tf32.tf32.f32 "
        "{%0,%1,%2,%3},{%4,%5,%6,%7},{%8,%9},{%0,%1,%2,%3};"
        : "+f"(c[0]), "+f"(c[1]), "+f"(c[2]), "+f"(c[3])
        : "r"(a0), "r"(a1), "r"(a2), "r"(a3), "r"(b0), "r"(b1));
}

// ---------------- positional encoding ----------------
__global__ void pe_kernel() {
    int idx = blockIdx.x * 256 + threadIdx.x;
    if (idx >= NR * 256) return;
    int r = idx >> 8;
    int m = idx & 255;
    double inv = exp(-((double)(2 * m) / 512.0) * log(10000.0));
    double ang = (double)(1023 - r) * inv;
    gPE[r * ND + 2 * m]     = (float)sin(ang);
    gPE[r * ND + 2 * m + 1] = (float)cos(ang);
}

// ---------------- C[M,512] = A[M,512] @ W[512,512]^T + bias (3xTF32) ------
// Block: 256 thr (8 warps, 4m x 2n), tile 128x64, k-chunk 32.
__global__ void proj_tc(const float* __restrict__ A, const float* __restrict__ W,
                        const float* __restrict__ bias, float* __restrict__ C, int M) {
    extern __shared__ unsigned sm[];
    unsigned* Ah = sm;                    // 128*PADK
    unsigned* Al = Ah + 128 * PADK;
    unsigned* Wh = Al + 128 * PADK;       // 64*PADK, stored [n][k]
    unsigned* Wl = Wh + 64 * PADK;
    int tid = threadIdx.x;
    int warp = tid >> 5, lane = tid & 31;
    int wm = warp >> 1, wn = warp & 1;
    int g = lane >> 2, t = lane & 3;
    int bm = blockIdx.y * 128, bn = blockIdx.x * 64;
    float acc[2][4][4] = {};

    for (int k0 = 0; k0 < 512; k0 += 32) {
        #pragma unroll
        for (int i = 0; i < 4; i++) {
            int idx = tid + i * 256;
            int row = idx >> 3, c4 = (idx & 7) << 2;
            int grow = bm + row;
            float4 av = (grow < M) ? *(const float4*)&A[(size_t)grow * 512 + k0 + c4]
                                   : make_float4(0.f, 0.f, 0.f, 0.f);
            float a4[4] = {av.x, av.y, av.z, av.w};
            #pragma unroll
            for (int j = 0; j < 4; j++)
                cvt_pair(a4[j], Ah[row * PADK + c4 + j], Al[row * PADK + c4 + j]);
        }
        #pragma unroll
        for (int i = 0; i < 2; i++) {
            int idx = tid + i * 256;
            int row = idx >> 3, c4 = (idx & 7) << 2;
            float4 wv = *(const float4*)&W[(size_t)(bn + row) * 512 + k0 + c4];
            float w4[4] = {wv.x, wv.y, wv.z, wv.w};
            #pragma unroll
            for (int j = 0; j < 4; j++)
                cvt_pair(w4[j], Wh[row * PADK + c4 + j], Wl[row * PADK + c4 + j]);
        }
        __syncthreads();
        #pragma unroll
        for (int kk = 0; kk < 32; kk += 8) {
            unsigned ah[2][4], al[2][4];
            #pragma unroll
            for (int mt = 0; mt < 2; mt++) {
                int ar = wm * 32 + mt * 16 + g;
                ah[mt][0] = Ah[ar * PADK + kk + t];
                ah[mt][1] = Ah[(ar + 8) * PADK + kk + t];
                ah[mt][2] = Ah[ar * PADK + kk + t + 4];
                ah[mt][3] = Ah[(ar + 8) * PADK + kk + t + 4];
                al[mt][0] = Al[ar * PADK + kk + t];
                al[mt][1] = Al[(ar + 8) * PADK + kk + t];
                al[mt][2] = Al[ar * PADK + kk + t + 4];
                al[mt][3] = Al[(ar + 8) * PADK + kk + t + 4];
            }
            #pragma unroll
            for (int nt = 0; nt < 4; nt++) {
                int nb = wn * 32 + nt * 8 + g;
                unsigned bh0 = Wh[nb * PADK + kk + t], bh1 = Wh[nb * PADK + kk + t + 4];
                unsigned bl0 = Wl[nb * PADK + kk + t], bl1 = Wl[nb * PADK + kk + t + 4];
                #pragma unroll
                for (int mt = 0; mt < 2; mt++) {
                    mma8(acc[mt][nt], ah[mt][0], ah[mt][1], ah[mt][2], ah[mt][3], bh0, bh1);
                    mma8(acc[mt][nt], ah[mt][0], ah[mt][1], ah[mt][2], ah[mt][3], bl0, bl1);
                    mma8(acc[mt][nt], al[mt][0], al[mt][1], al[mt][2], al[mt][3], bh0, bh1);
                }
            }
        }
        __syncthreads();
    }
    #pragma unroll
    for (int mt = 0; mt < 2; mt++) {
        #pragma unroll
        for (int nt = 0; nt < 4; nt++) {
            int row = bm + wm * 32 + mt * 16 + g;
            int col = bn + wn * 32 + nt * 8 + t * 2;
            if (row < M) {
                C[(size_t)row * 512 + col]     = acc[mt][nt][0] + bias[col];
                C[(size_t)row * 512 + col + 1] = acc[mt][nt][1] + bias[col + 1];
            }
            if (row + 8 < M) {
                C[(size_t)(row + 8) * 512 + col]     = acc[mt][nt][2] + bias[col];
                C[(size_t)(row + 8) * 512 + col + 1] = acc[mt][nt][3] + bias[col + 1];
            }
        }
    }
}

// ---------------- gUK / gVE -------------------------------------------
__global__ void uk_kernel(const float* __restrict__ u) {
    int gid = blockIdx.x * 256 + threadIdx.x;
    int w = gid >> 5, lane = gid & 31;
    if (w >= NB * NH * NT) return;
    int t = w & (NT - 1);
    int bh = w >> 10;
    int h = bh & 7, b = bh >> 3;
    const float* kp = gK + (size_t)(b * NT + t) * ND + h * NDH;
    const float* up = u + h * NDH;
    float s = kp[lane] * up[lane] + kp[lane + 32] * up[lane + 32];
    #pragma unroll
    for (int o = 16; o; o >>= 1) s += __shfl_down_sync(0xffffffffu, s, o);
    if (lane == 0) gUK[bh * NT + t] = s;
}

__global__ void ve_kernel(const float* __restrict__ v) {
    int gid = blockIdx.x * 256 + threadIdx.x;
    int w = gid >> 5, lane = gid & 31;
    if (w >= NH * NR) return;
    int h = w / NR;
    int r = w - h * NR;
    const float* ep = gE + (size_t)r * ND + h * NDH;
    const float* vp = v + h * NDH;
    float s = ep[lane] * vp[lane] + ep[lane + 32] * vp[lane + 32];
    #pragma unroll
    for (int o = 16; o; o >>= 1) s += __shfl_down_sync(0xffffffffu, s, o);
    if (lane == 0) gVE[h * NR + r] = s;
}

// ---------------- scores (tensor, 3xTF32) --------------------------------
// 64x64 tile per block, 256 thr, warps 4m x 2n (warp tile 16x32).
// Phase 1: Q.K^T. Phase 2: two 64-col chunks of skewed E-GEMM -> Gs.
// Epilogue: diagonal gather + uK + vE tables, scale, store.
__global__ void scores_tc() {
    extern __shared__ unsigned sm[];
    unsigned* Qh = sm;                    // 64*PADD
    unsigned* Ql = Qh + 64 * PADD;
    unsigned* Bh = Ql + 64 * PADD;        // K tile, then E chunks, [n][k]
    unsigned* Bl = Bh + 64 * PADD;
    float* Gs = (float*)(Bl + 64 * PADD); // 64*132
    int tid = threadIdx.x;
    int bh = blockIdx.z, h = bh & 7, b = bh >> 3;
    int q0 = blockIdx.y * 64, k0 = blockIdx.x * 64;
    int warp = tid >> 5, lane = tid & 31;
    int wm = warp >> 1, wn = warp & 1;
    int g = lane >> 2, t = lane & 3;

    #pragma unroll
    for (int i = 0; i < 4; i++) {
        int idx = tid + i * 256;
        int row = idx >> 4, c4 = (idx & 15) << 2;
        float4 qv = *(const float4*)&gQ[(size_t)(b * NT + q0 + row) * ND + h * NDH + c4];
        float4 kv = *(const float4*)&gK[(size_t)(b * NT + k0 + row) * ND + h * NDH + c4];
        float q4[4] = {qv.x, qv.y, qv.z, qv.w};
        float k4[4] = {kv.x, kv.y, kv.z, kv.w};
        #pragma unroll
        for (int j = 0; j < 4; j++) {
            cvt_pair(q4[j], Qh[row * PADD + c4 + j], Ql[row * PADD + c4 + j]);
            cvt_pair(k4[j], Bh[row * PADD + c4 + j], Bl[row * PADD + c4 + j]);
        }
    }
    __syncthreads();

    float accK[4][4] = {};
    int ar = wm * 16 + g;
    #pragma unroll
    for (int kk = 0; kk < 64; kk += 8) {
        unsigned ah[4], al[4];
        ah[0] = Qh[ar * PADD + kk + t];       ah[1] = Qh[(ar + 8) * PADD + kk + t];
        ah[2] = Qh[ar * PADD + kk + t + 4];   ah[3] = Qh[(ar + 8) * PADD + kk + t + 4];
        al[0] = Ql[ar * PADD + kk + t];       al[1] = Ql[(ar + 8) * PADD + kk + t];
        al[2] = Ql[ar * PADD + kk + t + 4];   al[3] = Ql[(ar + 8) * PADD + kk + t + 4];
        #pragma unroll
        for (int nt = 0; nt < 4; nt++) {
            int nb = wn * 32 + nt * 8 + g;
            unsigned bh0 = Bh[nb * PADD + kk + t], bh1 = Bh[nb * PADD + kk + t + 4];
            unsigned bl0 = Bl[nb * PADD + kk + t], bl1 = Bl[nb * PADD + kk + t + 4];
            mma8(accK[nt], ah[0], ah[1], ah[2], ah[3], bh0, bh1);
            mma8(accK[nt], ah[0], ah[1], ah[2], ah[3], bl0, bl1);
            mma8(accK[nt], al[0], al[1], al[2], al[3], bh0, bh1);
        }
    }

    int rbase = 960 + k0 - q0;   // >= 0 always
    for (int chunk = 0; chunk < 2; chunk++) {
        __syncthreads();
        #pragma unroll
        for (int i = 0; i < 4; i++) {
            int idx = tid + i * 256;
            int row = idx >> 4, c4 = (idx & 15) << 2;
            int r = rbase + chunk * 64 + row;
            float4 ev = (r < NR) ? *(const float4*)&gE[(size_t)r * ND + h * NDH + c4]
                                 : make_float4(0.f, 0.f, 0.f, 0.f);
            float e4[4] = {ev.x, ev.y, ev.z, ev.w};
            #pragma unroll
            for (int j = 0; j < 4; j++)
                cvt_pair(e4[j], Bh[row * PADD + c4 + j], Bl[row * PADD + c4 + j]);
        }
        __syncthreads();
        float accE[4][4] = {};
        #pragma unroll
        for (int kk = 0; kk < 64; kk += 8) {
            unsigned ah[4], al[4];
            ah[0] = Qh[ar * PADD + kk + t];       ah[1] = Qh[(ar + 8) * PADD + kk + t];
            ah[2] = Qh[ar * PADD + kk + t + 4];   ah[3] = Qh[(ar + 8) * PADD + kk + t + 4];
            al[0] = Ql[ar * PADD + kk + t];       al[1] = Ql[(ar + 8) * PADD + kk + t];
            al[2] = Ql[ar * PADD + kk + t + 4];   al[3] = Ql[(ar + 8) * PADD + kk + t + 4];
            #pragma unroll
            for (int nt = 0; nt < 4; nt++) {
                int nb = wn * 32 + nt * 8 + g;
                unsigned bh0 = Bh[nb * PADD + kk + t], bh1 = Bh[nb * PADD + kk + t + 4];
                unsigned bl0 = Bl[nb * PADD + kk + t], bl1 = Bl[nb * PADD + kk + t + 4];
                mma8(accE[nt], ah[0], ah[1], ah[2], ah[3], bh0, bh1);
                mma8(accE[nt], ah[0], ah[1], ah[2], ah[3], bl0, bl1);
                mma8(accE[nt], al[0], al[1], al[2], al[3], bh0, bh1);
            }
        }
        #pragma unroll
        for (int nt = 0; nt < 4; nt++) {
            int row = wm * 16 + g;
            int col = chunk * 64 + wn * 32 + nt * 8 + t * 2;
            Gs[row * 132 + col]           = accE[nt][0];
            Gs[row * 132 + col + 1]       = accE[nt][1];
            Gs[(row + 8) * 132 + col]     = accE[nt][2];
            Gs[(row + 8) * 132 + col + 1] = accE[nt][3];
        }
    }
    __syncthreads();

    #pragma unroll
    for (int nt = 0; nt < 4; nt++) {
        int qb = wm * 16 + g;
        int kb = wn * 32 + nt * 8 + t * 2;
        #pragma unroll
        for (int r4 = 0; r4 < 4; r4++) {
            int q = qb + ((r4 >= 2) ? 8 : 0);
            int k = kb + (r4 & 1);
            int c = k + 63 - q;
            float s = (accK[nt][r4] + Gs[q * 132 + c]
                       + gUK[bh * NT + k0 + k] + gVE[h * NR + rbase + c]) * 0.125f;
            gS[(size_t)(bh * NT + q0 + q) * NT + k0 + k] = s;
        }
    }
}

// ---------------- row softmax over 1024 columns --------------------------
__global__ void softmax_kernel() {
    int row = blockIdx.x;
    float* p = gS + (size_t)row * NT;
    int tid = threadIdx.x;
    float4 v = *(float4*)(p + tid * 4);
    __shared__ float red[256];
    float m = fmaxf(fmaxf(v.x, v.y), fmaxf(v.z, v.w));
    red[tid] = m; __syncthreads();
    for (int s = 128; s; s >>= 1) {
        if (tid < s) red[tid] = fmaxf(red[tid], red[tid + s]);
        __syncthreads();
    }
    m = red[0]; __syncthreads();
    v.x = expf(v.x - m); v.y = expf(v.y - m);
    v.z = expf(v.z - m); v.w = expf(v.w - m);
    float sum = v.x + v.y + v.z + v.w;
    red[tid] = sum; __syncthreads();
    for (int s = 128; s; s >>= 1) {
        if (tid < s) red[tid] += red[tid + s];
        __syncthreads();
    }
    float inv = 1.f / red[0];
    v.x *= inv; v.y *= inv; v.z *= inv; v.w *= inv;
    *(float4*)(p + tid * 4) = v;
}

// ---------------- O = P @ V (tensor, 3xTF32) -----------------------------
// Block: 256 thr, output 128(q) x 64(d) per (bh, q-tile). k = 1024, chunk 32.
__global__ void pv_tc() {
    extern __shared__ unsigned sm[];
    unsigned* Ph = sm;                    // 128*PADK
    unsigned* Pl = Ph + 128 * PADK;
    unsigned* Vh = Pl + 128 * PADK;       // 32*PADD, stored [k=pos][n=d]
    unsigned* Vl = Vh + 32 * PADD;
    int tid = threadIdx.x;
    int warp = tid >> 5, lane = tid & 31;
    int wm = warp >> 1, wn = warp & 1;
    int g = lane >> 2, t = lane & 3;
    int bh = blockIdx.y, b = bh >> 3, h = bh & 7;
    int q0 = blockIdx.x * 128;
    float acc[2][4][4] = {};

    for (int kk0 = 0; kk0 < NT; kk0 += 32) {
        #pragma unroll
        for (int i = 0; i < 4; i++) {
            int idx = tid + i * 256;
            int row = idx >> 3, c4 = (idx & 7) << 2;
            float4 pv = *(const float4*)&gS[(size_t)(bh * NT + q0 + row) * NT + kk0 + c4];
            float p4[4] = {pv.x, pv.y, pv.z, pv.w};
            #pragma unroll
            for (int j = 0; j < 4; j++)
                cvt_pair(p4[j], Ph[row * PADK + c4 + j], Pl[row * PADK + c4 + j]);
        }
        #pragma unroll
        for (int i = 0; i < 2; i++) {
            int idx = tid + i * 256;
            int pos = idx >> 4, c4 = (idx & 15) << 2;
            float4 vv = *(const float4*)&gV[(size_t)(b * NT + kk0 + pos) * ND + h * NDH + c4];
            float v4[4] = {vv.x, vv.y, vv.z, vv.w};
            #pragma unroll
            for (int j = 0; j < 4; j++)
                cvt_pair(v4[j], Vh[pos * PADD + c4 + j], Vl[pos * PADD + c4 + j]);
        }
        __syncthreads();
        #pragma unroll
        for (int kk = 0; kk < 32; kk += 8) {
            unsigned ah[2][4], al[2][4];
            #pragma unroll
            for (int mt = 0; mt < 2; mt++) {
                int arow = wm * 32 + mt * 16 + g;
                ah[mt][0] = Ph[arow * PADK + kk + t];
                ah[mt][1] = Ph[(arow + 8) * PADK + kk + t];
                ah[mt][2] = Ph[arow * PADK + kk + t + 4];
                ah[mt][3] = Ph[(arow + 8) * PADK + kk + t + 4];
                al[mt][0] = Pl[arow * PADK + kk + t];
                al[mt][1] = Pl[(arow + 8) * PADK + kk + t];
                al[mt][2] = Pl[arow * PADK + kk + t + 4];
                al[mt][3] = Pl[(arow + 8) * PADK + kk + t + 4];
            }
            #pragma unroll
            for (int nt = 0; nt < 4; nt++) {
                int nb = wn * 32 + nt * 8 + g;
                unsigned bh0 = Vh[(kk + t) * PADD + nb],     bh1 = Vh[(kk + t + 4) * PADD + nb];
                unsigned bl0 = Vl[(kk + t) * PADD + nb],     bl1 = Vl[(kk + t + 4) * PADD + nb];
                #pragma unroll
                for (int mt = 0; mt < 2; mt++) {
                    mma8(acc[mt][nt], ah[mt][0], ah[mt][1], ah[mt][2], ah[mt][3], bh0, bh1);
                    mma8(acc[mt][nt], ah[mt][0], ah[mt][1], ah[mt][2], ah[mt][3], bl0, bl1);
                    mma8(acc[mt][nt], al[mt][0], al[mt][1], al[mt][2], al[mt][3], bh0, bh1);
                }
            }
        }
        __syncthreads();
    }
    #pragma unroll
    for (int mt = 0; mt < 2; mt++) {
        #pragma unroll
        for (int nt = 0; nt < 4; nt++) {
            int row = q0 + wm * 32 + mt * 16 + g;
            int col = wn * 32 + nt * 8 + t * 2;
            gO[(size_t)(b * NT + row) * ND + h * NDH + col]           = acc[mt][nt][0];
            gO[(size_t)(b * NT + row) * ND + h * NDH + col + 1]       = acc[mt][nt][1];
            gO[(size_t)(b * NT + row + 8) * ND + h * NDH + col]       = acc[mt][nt][2];
            gO[(size_t)(b * NT + row + 8) * ND + h * NDH + col + 1]   = acc[mt][nt][3];
        }
    }
}

// -------------------------------------------------------------------------
extern "C" void kernel_launch(void* const* d_in, const int* in_sizes, int n_in,
                              void* d_out, int out_size) {
    const float* query = (const float*)d_in[0];
    const float* key_  = (const float*)d_in[1];
    const float* value = (const float*)d_in[2];
    const float* Wq = (const float*)d_in[3];
    const float* bq = (const float*)d_in[4];
    const float* Wk = (const float*)d_in[5];
    const float* bk = (const float*)d_in[6];
    const float* Wv = (const float*)d_in[7];
    const float* bv = (const float*)d_in[8];
    const float* Wp = (const float*)d_in[9];
    const float* bp = (const float*)d_in[10];
    const float* Wo = (const float*)d_in[11];
    const float* bo = (const float*)d_in[12];
    const float* ub = (const float*)d_in[13];
    const float* vb = (const float*)d_in[14];
    float* out = (float*)d_out;

    float *pQ, *pK, *pV, *pPE, *pE, *pO;
    cudaGetSymbolAddress((void**)&pQ, gQ);
    cudaGetSymbolAddress((void**)&pK, gK);
    cudaGetSymbolAddress((void**)&pV, gV);
    cudaGetSymbolAddress((void**)&pPE, gPE);
    cudaGetSymbolAddress((void**)&pE, gE);
    cudaGetSymbolAddress((void**)&pO, gO);

    const int PROJ_SMEM   = (2 * 128 * PADK + 2 * 64 * PADK) * 4;              // 55296
    const int SCORES_SMEM = (4 * 64 * PADD) * 4 + (64 * 132) * 4;              // 103424
    const int PV_SMEM     = (2 * 128 * PADK + 2 * 32 * PADD) * 4;              // 54272
    cudaFuncSetAttribute(proj_tc,   cudaFuncAttributeMaxDynamicSharedMemorySize, PROJ_SMEM);
    cudaFuncSetAttribute(scores_tc, cudaFuncAttributeMaxDynamicSharedMemorySize, SCORES_SMEM);
    cudaFuncSetAttribute(pv_tc,     cudaFuncAttributeMaxDynamicSharedMemorySize, PV_SMEM);

    pe_kernel<<<NR, 256>>>();
    proj_tc<<<dim3(8, 32), 256, PROJ_SMEM>>>(query, Wq, bq, pQ, NM);
    proj_tc<<<dim3(8, 32), 256, PROJ_SMEM>>>(key_,  Wk, bk, pK, NM);
    proj_tc<<<dim3(8, 32), 256, PROJ_SMEM>>>(value, Wv, bv, pV, NM);
    proj_tc<<<dim3(8, 16), 256, PROJ_SMEM>>>(pPE,   Wp, bp, pE, NR);
    uk_kernel<<<(NB * NH * NT * 32) / 256, 256>>>(ub);
    ve_kernel<<<(NH * NR * 32 + 255) / 256, 256>>>(vb);
    scores_tc<<<dim3(16, 16, 32), 256, SCORES_SMEM>>>();
    softmax_kernel<<<NB * NH * NT, 256>>>();
    pv_tc<<<dim3(8, 32), 256, PV_SMEM>>>();
    proj_tc<<<dim3(8, 32), 256, PROJ_SMEM>>>(pO, Wo, bo, out, NM);
}